// round 10
// baseline (speedup 1.0000x reference)
#include <cuda_runtime.h>
#include <cstdint>
#include <cstddef>

#define NROWS 16384
#define DIN 128
#define DH 16
#define DOUT 4

typedef unsigned long long u64;
typedef unsigned int u32;

// Scratch (device globals: allocations are forbidden)
__device__ float g_WT[2 * DH * NROWS]; // rows 0-15: tf32_hi((X@W1)^T), rows 16-31: tf32_lo
__device__ float g_HW2[NROWS * DOUT];  // relu(...) @ W2  [16384,4]

// ---------------- PTX helpers ----------------
__device__ __forceinline__ void cp_async16(void* smem_ptr, const void* gmem_ptr) {
    unsigned saddr = (unsigned)__cvta_generic_to_shared(smem_ptr);
    asm volatile("cp.async.cg.shared.global [%0], [%1], 16;\n" :: "r"(saddr), "l"(gmem_ptr));
}
__device__ __forceinline__ void cp_commit() { asm volatile("cp.async.commit_group;\n"); }
template <int N>
__device__ __forceinline__ void cp_wait() { asm volatile("cp.async.wait_group %0;\n" :: "n"(N)); }

__device__ __forceinline__ u64 dup2(float a) {
    u64 r; asm("mov.b64 %0, {%1, %1};" : "=l"(r) : "f"(a)); return r;
}
__device__ __forceinline__ void fma2(u64& acc, u64 a, u64 b) {
    asm("fma.rn.f32x2 %0, %1, %2, %0;" : "+l"(acc) : "l"(a), "l"(b));
}
__device__ __forceinline__ u32 cvt_tf32(float x) {
    u32 r; asm("cvt.rna.tf32.f32 %0, %1;" : "=r"(r) : "f"(x)); return r;
}
// m16n8k8 tf32 HMMA (base sm_80+ ISA, valid on non-'a' sm_103 target)
__device__ __forceinline__ void mma_tf32(float4& d, u32 a0, u32 a1, u32 a2, u32 a3,
                                         u32 b0, u32 b1) {
    asm volatile("mma.sync.aligned.m16n8k8.row.col.f32.tf32.tf32.f32 "
                 "{%0,%1,%2,%3}, {%4,%5,%6,%7}, {%8,%9}, {%0,%1,%2,%3};"
                 : "+f"(d.x), "+f"(d.y), "+f"(d.z), "+f"(d.w)
                 : "r"(a0), "r"(a1), "r"(a2), "r"(a3), "r"(b0), "r"(b1));
}

// Diagnostic no-ops: ncu profiles launch index 3 -> land it on pass1_mma.
__global__ void dummy_a() {}
__global__ void dummy_b() {}

// ---------------- Kernel 0: WT_hi/lo = tf32-split of (X @ W1)^T ----------------
__global__ __launch_bounds__(256)
void xw1t_kernel(const float* __restrict__ X, const float* __restrict__ W1,
                 float* __restrict__ WT) {
    __shared__ float xs[32 * DIN];
    __shared__ float w1s[DIN * DH];
    const int tid = threadIdx.x;
    for (int i = tid; i < DIN * DH / 2; i += 256)
        ((float2*)w1s)[i] = ((const float2*)W1)[i];
    const float4* xg = (const float4*)(X + (size_t)blockIdx.x * 32 * DIN);
#pragma unroll
    for (int t = 0; t < 4; t++)
        ((float4*)xs)[t * 256 + tid] = xg[t * 256 + tid];
    __syncthreads();
#pragma unroll
    for (int t = 0; t < 2; t++) {
        int i = t * 256 + tid;
        int r = i >> 4, c = i & 15;
        float acc = 0.0f;
#pragma unroll
        for (int k = 0; k < DIN; k++) acc += xs[r * DIN + k] * w1s[k * DH + c];
        u32 hi = cvt_tf32(acc);
        float lo = acc - __uint_as_float(hi);
        size_t col = (size_t)blockIdx.x * 32 + r;
        WT[(size_t)c * NROWS + col]        = __uint_as_float(hi);
        WT[(size_t)(DH + c) * NROWS + col] = __uint_as_float(cvt_tf32(lo));
    }
}

// ---------------- Pass 1 (HMMA 3xTF32): HW2 = relu(A @ XW1 + b1) @ W2 ----------------
// BM=128, BK=64, 4-deep cp.async pipeline (2-3 stages in flight during compute).
// 512 threads, 16 warps = (ksplit 0..7) x (m-half 0..1); warp computes 4 m16-tiles.
__global__ __launch_bounds__(512, 1)
void pass1_mma(const float* __restrict__ A, const float* __restrict__ WT,
               const float* __restrict__ b1, const float* __restrict__ W2,
               float* __restrict__ out) {
    constexpr int BM = 128, BK = 64;
    constexpr int STRIDE = 68;                // 64 + 4 pad: conflict-free
    constexpr int NST = NROWS / BK;           // 256
    constexpr int ABUF = BM * STRIDE;         // 8704 floats
    constexpr int WBUF = 2 * DH * STRIDE;     // 2176 floats (hi+lo, 32 rows)
    constexpr int SB = ABUF + WBUF;           // 10880 floats per stage
    constexpr int NBUF = 4;

    extern __shared__ float fsm[];
    const int tid  = threadIdx.x;
    const int w    = tid >> 5;
    const int lane = tid & 31;
    const int gid  = lane >> 2;               // 0..7
    const int tig  = lane & 3;                // 0..3
    const int ks   = w & 7;                   // k offset = ks*8 within BK=64
    const int mh   = w >> 3;                  // m-half: tiles mh*4 .. mh*4+3
    const int row0 = blockIdx.x * BM;

    auto load_stage = [&](int s) {
        float* base = fsm + (s & (NBUF - 1)) * SB;
        const size_t kb = (size_t)s * BK;
#pragma unroll
        for (int t = 0; t < 4; t++) {          // A: 128 rows x 16 chunks = 2048 float4
            int idx = t * 512 + tid;
            int r = idx >> 4, c4 = idx & 15;
            cp_async16(base + r * STRIDE + c4 * 4,
                       A + (size_t)(row0 + r) * NROWS + kb + c4 * 4);
        }
        {                                      // WT hi+lo: 32 rows x 16 chunks = 512 float4
            int r = tid >> 4, c4 = tid & 15;
            cp_async16(base + ABUF + r * STRIDE + c4 * 4,
                       WT + (size_t)r * NROWS + kb + c4 * 4);
        }
        cp_commit();
    };

    load_stage(0);
    load_stage(1);
    load_stage(2);

    float4 C[4][2];                            // [mtile within half][ntile]
#pragma unroll
    for (int m = 0; m < 4; m++)
#pragma unroll
        for (int n = 0; n < 2; n++) C[m][n] = make_float4(0.f, 0.f, 0.f, 0.f);

    for (int s = 0; s < NST; s++) {
        cp_wait<2>();                          // group s complete (1 commit per iter)
        __syncthreads();
        const float* base = fsm + (s & (NBUF - 1)) * SB;
        const int k0 = ks * 8;
        const float* bh = base + ABUF + gid * STRIDE + k0 + tig;
        const float* bl = bh + DH * STRIDE;
        u32 bh00 = __float_as_uint(bh[0]);
        u32 bh01 = __float_as_uint(bh[4]);
        u32 bh10 = __float_as_uint(bh[8 * STRIDE]);
        u32 bh11 = __float_as_uint(bh[8 * STRIDE + 4]);
        u32 bl00 = __float_as_uint(bl[0]);
        u32 bl01 = __float_as_uint(bl[4]);
        u32 bl10 = __float_as_uint(bl[8 * STRIDE]);
        u32 bl11 = __float_as_uint(bl[8 * STRIDE + 4]);
#pragma unroll
        for (int mt = 0; mt < 4; mt++) {
            const float* ap = base + (mh * 64 + mt * 16 + gid) * STRIDE + k0 + tig;
            float av0 = ap[0], av1 = ap[8 * STRIDE], av2 = ap[4], av3 = ap[8 * STRIDE + 4];
            u32 ah0 = cvt_tf32(av0), ah1 = cvt_tf32(av1);
            u32 ah2 = cvt_tf32(av2), ah3 = cvt_tf32(av3);
            u32 al0 = cvt_tf32(av0 - __uint_as_float(ah0));
            u32 al1 = cvt_tf32(av1 - __uint_as_float(ah1));
            u32 al2 = cvt_tf32(av2 - __uint_as_float(ah2));
            u32 al3 = cvt_tf32(av3 - __uint_as_float(ah3));
            mma_tf32(C[mt][0], ah0, ah1, ah2, ah3, bh00, bh01);
            mma_tf32(C[mt][0], al0, al1, al2, al3, bh00, bh01);
            mma_tf32(C[mt][0], ah0, ah1, ah2, ah3, bl00, bl01);
            mma_tf32(C[mt][1], ah0, ah1, ah2, ah3, bh10, bh11);
            mma_tf32(C[mt][1], al0, al1, al2, al3, bh10, bh11);
            mma_tf32(C[mt][1], ah0, ah1, ah2, ah3, bl10, bl11);
        }
        __syncthreads();
        if (s + 3 < NST) load_stage(s + 3); else cp_commit();   // keep 1 commit/iter
    }

    // ---- epilogue: reduce 8 ksplit partials, bias+relu, fuse H@W2 ----
    float* psum = fsm;                         // [8][128][16] = 64 KB
    {
        float* p = psum + ks * (BM * DH);
#pragma unroll
        for (int mt = 0; mt < 4; mt++) {
            const int rb = mh * 64 + mt * 16 + gid;
            *(float2*)(p + rb * DH + 2 * tig)           = make_float2(C[mt][0].x, C[mt][0].y);
            *(float2*)(p + (rb + 8) * DH + 2 * tig)     = make_float2(C[mt][0].z, C[mt][0].w);
            *(float2*)(p + rb * DH + 8 + 2 * tig)       = make_float2(C[mt][1].x, C[mt][1].y);
            *(float2*)(p + (rb + 8) * DH + 8 + 2 * tig) = make_float2(C[mt][1].z, C[mt][1].w);
        }
    }
    __syncthreads();
    float* hbuf = fsm + 8 * BM * DH;           // [128][16] = 8 KB, after psum
#pragma unroll
    for (int t = 0; t < 4; t++) {
        int i = t * 512 + tid;                 // 2048 h values
        float sum = 0.0f;
#pragma unroll
        for (int sp = 0; sp < 8; sp++) sum += psum[sp * (BM * DH) + i];
        sum += __ldg(&b1[i & 15]);
        hbuf[i] = fmaxf(sum, 0.0f);
    }
    __syncthreads();
    {
        const int r = tid >> 2, c = tid & 3;   // 512 outputs = 128 rows x 4
        float o = 0.0f;
#pragma unroll
        for (int j = 0; j < DH; j++)
            o += hbuf[r * DH + j] * __ldg(&W2[j * DOUT + c]);
        out[(size_t)(row0 + r) * DOUT + c] = o;
    }
}

// ---------------- Pass 2 (SIMT, memory-bound): logits = A @ HW2 + b2 ----------------
__global__ __launch_bounds__(256, 2)
void pass2_kernel(const float* __restrict__ A, const float* __restrict__ W,
                  const float* __restrict__ bias, float* __restrict__ out) {
    constexpr int NCOL = 4;
    constexpr int BM = 64, BK = 128;
    constexpr int STRIDE = 132;
    constexpr int NST = NROWS / BK;
    constexpr int ABUF = BM * STRIDE;
    constexpr int WBUF = BK * NCOL;

    extern __shared__ float fsm[];
    float* As[2] = { fsm, fsm + ABUF };
    float* Ws[2] = { fsm + 2 * ABUF, fsm + 2 * ABUF + WBUF };

    const int tid  = threadIdx.x;
    const int w    = tid >> 5;                // ksplit 0..7 (16 k's)
    const int lane = tid & 31;
    const int row0 = blockIdx.x * BM;

    auto load_stage = [&](int s) {
        const int buf = s & 1;
        const size_t kbase = (size_t)s * BK;
#pragma unroll
        for (int t = 0; t < 8; t++) {
            int idx = t * 256 + tid;
            int r = idx >> 5, c4 = idx & 31;
            cp_async16(As[buf] + r * STRIDE + c4 * 4,
                       A + (size_t)(row0 + r) * NROWS + kbase + c4 * 4);
        }
        if (tid < WBUF / 4)
            cp_async16(Ws[buf] + tid * 4, W + kbase * NCOL + tid * 4);
        cp_commit();
    };

    load_stage(0);
    load_stage(1);

    u64 acc[2][2] = {{0ull, 0ull}, {0ull, 0ull}};   // [rowhalf][colpair]

    for (int s = 0; s < NST; s++) {
        if (s + 1 < NST) cp_wait<1>(); else cp_wait<0>();
        __syncthreads();
        const int buf = s & 1;
        const float* ab = As[buf] + lane * STRIDE + w * 16;
        const float* wp = Ws[buf] + w * 16 * NCOL;
#pragma unroll
        for (int kh = 0; kh < 4; kh++) {
            float4 a0 = *(const float4*)(ab + kh * 4);
            float4 a1 = *(const float4*)(ab + 32 * STRIDE + kh * 4);
#pragma unroll
            for (int k2 = 0; k2 < 4; k2++) {
                const int k = kh * 4 + k2;
                ulonglong2 wv = *(const ulonglong2*)(wp + k * NCOL);  // warp-uniform
                u64 d0 = dup2(((const float*)&a0)[k2]);
                u64 d1 = dup2(((const float*)&a1)[k2]);
                fma2(acc[0][0], d0, wv.x);
                fma2(acc[0][1], d0, wv.y);
                fma2(acc[1][0], d1, wv.x);
                fma2(acc[1][1], d1, wv.y);
            }
        }
        __syncthreads();
        if (s + 2 < NST) load_stage(s + 2);
    }

    float* pbuf = fsm;                         // [8][64][4] = 8 KB
#pragma unroll
    for (int rh = 0; rh < 2; rh++)
        *(float4*)(pbuf + (size_t)(w * BM + lane + rh * 32) * NCOL) =
            make_float4(__uint_as_float((u32)acc[rh][0]),
                        __uint_as_float((u32)(acc[rh][0] >> 32)),
                        __uint_as_float((u32)acc[rh][1]),
                        __uint_as_float((u32)(acc[rh][1] >> 32)));
    __syncthreads();

    const int r = tid >> 2, c = tid & 3;
    float sum = 0.0f;
#pragma unroll
    for (int sp = 0; sp < 8; sp++) sum += pbuf[(size_t)(sp * BM + r) * NCOL + c];
    sum += __ldg(&bias[c]);
    out[(size_t)(row0 + r) * NCOL + c] = sum;
}

// ---------------- launch ----------------
extern "C" void kernel_launch(void* const* d_in, const int* in_sizes, int n_in,
                              void* d_out, int out_size) {
    const float* A  = (const float*)d_in[0];
    const float* X  = (const float*)d_in[1];
    const float* W1 = (const float*)d_in[2];
    const float* b1 = (const float*)d_in[3];
    const float* W2 = (const float*)d_in[4];
    const float* b2 = (const float*)d_in[5];
    float* out = (float*)d_out;

    float *wtp, *hw2p;
    cudaGetSymbolAddress((void**)&wtp, g_WT);
    cudaGetSymbolAddress((void**)&hw2p, g_HW2);

    // #0, #1: no-ops so ncu's captured launch (index 3) is pass1_mma
    dummy_a<<<1, 32>>>();
    dummy_b<<<1, 32>>>();

    // #2) WT = tf32-split (X @ W1)^T
    xw1t_kernel<<<NROWS / 32, 256>>>(X, W1, wtp);

    // #3) HW2 = relu(A @ XW1 + b1) @ W2   (mma.sync 3xTF32, BM=128/BK=64, 4-deep)
    constexpr int SMEM_P1 = 4 * (128 * 68 + 32 * 68) * 4;    // 174080 B
    cudaFuncSetAttribute(pass1_mma, cudaFuncAttributeMaxDynamicSharedMemorySize, SMEM_P1);
    pass1_mma<<<NROWS / 128, 512, SMEM_P1>>>(A, wtp, b1, W2, hw2p);

    // #4) logits = A @ HW2 + b2           (SIMT, memory-bound)
    constexpr int SMEM_P2 = (2 * 64 * 132 + 2 * 128 * 4) * 4; // 71680 B
    cudaFuncSetAttribute(pass2_kernel, cudaFuncAttributeMaxDynamicSharedMemorySize, SMEM_P2);
    pass2_kernel<<<NROWS / 64, 256, SMEM_P2>>>(A, hw2p, b2, out);
}

// round 12
// speedup vs baseline: 1.0609x; 1.0609x over previous
#include <cuda_runtime.h>
#include <cstdint>
#include <cstddef>

#define NROWS 16384
#define DIN 128
#define DH 16
#define DOUT 4

typedef unsigned long long u64;
typedef unsigned int u32;

// Scratch (device globals: allocations are forbidden)
__device__ float g_WT[2 * DH * NROWS]; // rows 0-15: tf32_hi((X@W1)^T), rows 16-31: tf32_lo
__device__ float g_P[2 * NROWS * DH];  // pass1 partials: [khalf][row][16]
__device__ float g_HW2[NROWS * DOUT];  // relu(...) @ W2  [16384,4]

// ---------------- PTX helpers ----------------
__device__ __forceinline__ void cp_async16(void* smem_ptr, const void* gmem_ptr) {
    unsigned saddr = (unsigned)__cvta_generic_to_shared(smem_ptr);
    asm volatile("cp.async.cg.shared.global [%0], [%1], 16;\n" :: "r"(saddr), "l"(gmem_ptr));
}
__device__ __forceinline__ void cp_commit() { asm volatile("cp.async.commit_group;\n"); }
template <int N>
__device__ __forceinline__ void cp_wait() { asm volatile("cp.async.wait_group %0;\n" :: "n"(N)); }

__device__ __forceinline__ u64 dup2(float a) {
    u64 r; asm("mov.b64 %0, {%1, %1};" : "=l"(r) : "f"(a)); return r;
}
__device__ __forceinline__ void fma2(u64& acc, u64 a, u64 b) {
    asm("fma.rn.f32x2 %0, %1, %2, %0;" : "+l"(acc) : "l"(a), "l"(b));
}
__device__ __forceinline__ u32 cvt_tf32(float x) {
    u32 r; asm("cvt.rna.tf32.f32 %0, %1;" : "=r"(r) : "f"(x)); return r;
}
// m16n8k8 tf32 HMMA (base sm_80+ ISA, valid on non-'a' sm_103 target)
__device__ __forceinline__ void mma_tf32(float4& d, u32 a0, u32 a1, u32 a2, u32 a3,
                                         u32 b0, u32 b1) {
    asm volatile("mma.sync.aligned.m16n8k8.row.col.f32.tf32.tf32.f32 "
                 "{%0,%1,%2,%3}, {%4,%5,%6,%7}, {%8,%9}, {%0,%1,%2,%3};"
                 : "+f"(d.x), "+f"(d.y), "+f"(d.z), "+f"(d.w)
                 : "r"(a0), "r"(a1), "r"(a2), "r"(a3), "r"(b0), "r"(b1));
}

// Diagnostic no-ops: ncu profiles launch index 3 -> land it on pass1_mma.
__global__ void dummy_a() {}
__global__ void dummy_b() {}

// ---------------- Kernel 0: WT_hi/lo = tf32-split of (X @ W1)^T ----------------
__global__ __launch_bounds__(256)
void xw1t_kernel(const float* __restrict__ X, const float* __restrict__ W1,
                 float* __restrict__ WT) {
    __shared__ float xs[32 * DIN];
    __shared__ float w1s[DIN * DH];
    const int tid = threadIdx.x;
    for (int i = tid; i < DIN * DH / 2; i += 256)
        ((float2*)w1s)[i] = ((const float2*)W1)[i];
    const float4* xg = (const float4*)(X + (size_t)blockIdx.x * 32 * DIN);
#pragma unroll
    for (int t = 0; t < 4; t++)
        ((float4*)xs)[t * 256 + tid] = xg[t * 256 + tid];
    __syncthreads();
#pragma unroll
    for (int t = 0; t < 2; t++) {
        int i = t * 256 + tid;
        int r = i >> 4, c = i & 15;
        float acc = 0.0f;
#pragma unroll
        for (int k = 0; k < DIN; k++) acc += xs[r * DIN + k] * w1s[k * DH + c];
        u32 hi = cvt_tf32(acc);
        float lo = acc - __uint_as_float(hi);
        size_t col = (size_t)blockIdx.x * 32 + r;
        WT[(size_t)c * NROWS + col]        = __uint_as_float(hi);
        WT[(size_t)(DH + c) * NROWS + col] = __uint_as_float(cvt_tf32(lo));
    }
}

// ---------------- Pass 1 (HMMA 3xTF32, CTA K-split): P = A @ XW1 partials ----------------
// grid 256 = (row-block 0..127) x (k-half 0..1); 2 CTAs co-resident per SM.
// BM=128, BK=64, double-buffer; 8 warps = (ksplit 0..3) x (m-half 0..1).
__global__ __launch_bounds__(256, 2)
void pass1_mma(const float* __restrict__ A, const float* __restrict__ WT,
               float* __restrict__ P) {
    constexpr int BM = 128, BK = 64;
    constexpr int STRIDE = 68;                // 64 + 4 pad: conflict-free
    constexpr int KSPAN = NROWS / 2;          // 8192 per CTA
    constexpr int NST = KSPAN / BK;           // 128
    constexpr int ABUF = BM * STRIDE;         // 8704 floats
    constexpr int WBUF = 2 * DH * STRIDE;     // 2176 floats (hi+lo)
    constexpr int SB = ABUF + WBUF;           // 10880 floats/stage -> 87 KB total

    extern __shared__ float fsm[];
    const int tid  = threadIdx.x;
    const int w    = tid >> 5;
    const int lane = tid & 31;
    const int gid  = lane >> 2;               // 0..7
    const int tig  = lane & 3;                // 0..3
    const int ks   = w & 3;                   // k offset = ks*16 within BK=64
    const int mh   = w >> 2;                  // m-half: tiles mh*4 .. mh*4+3
    const int rb   = blockIdx.x >> 1;         // row block
    const int kc   = blockIdx.x & 1;          // k half
    const int row0 = rb * BM;
    const size_t kbase0 = (size_t)kc * KSPAN;

    auto load_stage = [&](int s) {
        float* base = fsm + (s & 1) * SB;
        const size_t kb = kbase0 + (size_t)s * BK;
        // A: 128 rows x 16 chunks(16B) = 2048 float4, 8 per thread
#pragma unroll
        for (int t = 0; t < 8; t++) {
            int idx = t * 256 + tid;
            int r = idx >> 4, c4 = idx & 15;
            cp_async16(base + r * STRIDE + c4 * 4,
                       A + (size_t)(row0 + r) * NROWS + kb + c4 * 4);
        }
        // WT hi+lo: 32 rows x 16 chunks = 512 float4, 2 per thread
#pragma unroll
        for (int t = 0; t < 2; t++) {
            int idx = t * 256 + tid;
            int r = idx >> 4, c4 = idx & 15;
            cp_async16(base + ABUF + r * STRIDE + c4 * 4,
                       WT + (size_t)r * NROWS + kb + c4 * 4);
        }
        cp_commit();
    };

    load_stage(0);
    load_stage(1);

    float4 C[4][2];                            // [mtile within half][ntile]
#pragma unroll
    for (int m = 0; m < 4; m++)
#pragma unroll
        for (int n = 0; n < 2; n++) C[m][n] = make_float4(0.f, 0.f, 0.f, 0.f);

    for (int s = 0; s < NST; s++) {
        if (s + 1 < NST) cp_wait<1>(); else cp_wait<0>();
        __syncthreads();
        const float* base = fsm + (s & 1) * SB;
#pragma unroll
        for (int k8 = 0; k8 < 2; k8++) {       // warp covers 16 k's = 2 k8 steps
            const int k0 = ks * 16 + k8 * 8;
            const float* bh = base + ABUF + gid * STRIDE + k0 + tig;
            const float* bl = bh + DH * STRIDE;
            u32 bh00 = __float_as_uint(bh[0]);
            u32 bh01 = __float_as_uint(bh[4]);
            u32 bh10 = __float_as_uint(bh[8 * STRIDE]);
            u32 bh11 = __float_as_uint(bh[8 * STRIDE + 4]);
            u32 bl00 = __float_as_uint(bl[0]);
            u32 bl01 = __float_as_uint(bl[4]);
            u32 bl10 = __float_as_uint(bl[8 * STRIDE]);
            u32 bl11 = __float_as_uint(bl[8 * STRIDE + 4]);
#pragma unroll
            for (int mt = 0; mt < 4; mt++) {
                const float* ap = base + (mh * 64 + mt * 16 + gid) * STRIDE + k0 + tig;
                float av0 = ap[0], av1 = ap[8 * STRIDE], av2 = ap[4], av3 = ap[8 * STRIDE + 4];
                u32 ah0 = cvt_tf32(av0), ah1 = cvt_tf32(av1);
                u32 ah2 = cvt_tf32(av2), ah3 = cvt_tf32(av3);
                u32 al0 = cvt_tf32(av0 - __uint_as_float(ah0));
                u32 al1 = cvt_tf32(av1 - __uint_as_float(ah1));
                u32 al2 = cvt_tf32(av2 - __uint_as_float(ah2));
                u32 al3 = cvt_tf32(av3 - __uint_as_float(ah3));
                mma_tf32(C[mt][0], ah0, ah1, ah2, ah3, bh00, bh01);
                mma_tf32(C[mt][0], al0, al1, al2, al3, bh00, bh01);
                mma_tf32(C[mt][0], ah0, ah1, ah2, ah3, bl00, bl01);
                mma_tf32(C[mt][1], ah0, ah1, ah2, ah3, bh10, bh11);
                mma_tf32(C[mt][1], al0, al1, al2, al3, bh10, bh11);
                mma_tf32(C[mt][1], ah0, ah1, ah2, ah3, bl10, bl11);
            }
        }
        __syncthreads();
        if (s + 2 < NST) load_stage(s + 2); else cp_commit();
    }

    // ---- epilogue: reduce 4 ksplit partials, write raw partial sums ----
    float* psum = fsm;                         // [4][128][16] = 32 KB
    {
        float* p = psum + ks * (BM * DH);
#pragma unroll
        for (int mt = 0; mt < 4; mt++) {
            const int rbm = mh * 64 + mt * 16 + gid;
            *(float2*)(p + rbm * DH + 2 * tig)           = make_float2(C[mt][0].x, C[mt][0].y);
            *(float2*)(p + (rbm + 8) * DH + 2 * tig)     = make_float2(C[mt][0].z, C[mt][0].w);
            *(float2*)(p + rbm * DH + 8 + 2 * tig)       = make_float2(C[mt][1].x, C[mt][1].y);
            *(float2*)(p + (rbm + 8) * DH + 8 + 2 * tig) = make_float2(C[mt][1].z, C[mt][1].w);
        }
    }
    __syncthreads();
    float* Pout = P + ((size_t)kc * NROWS + row0) * DH;
#pragma unroll
    for (int t = 0; t < 8; t++) {
        int i = t * 256 + tid;                 // 2048 values, coalesced
        float sum = 0.0f;
#pragma unroll
        for (int sp = 0; sp < 4; sp++) sum += psum[sp * (BM * DH) + i];
        Pout[i] = sum;
    }
}

// ---------------- Combine: HW2 = relu(P0 + P1 + b1) @ W2 ----------------
__global__ __launch_bounds__(256)
void combine_kernel(const float* __restrict__ P, const float* __restrict__ b1,
                    const float* __restrict__ W2, float* __restrict__ HW2) {
    const int row = blockIdx.x * 256 + threadIdx.x;
    const float4* p0 = (const float4*)(P + (size_t)row * DH);
    const float4* p1 = (const float4*)(P + (size_t)(NROWS + row) * DH);
    float o0 = 0.f, o1 = 0.f, o2 = 0.f, o3 = 0.f;
#pragma unroll
    for (int q = 0; q < 4; q++) {
        float4 a = p0[q], b = p1[q];
#pragma unroll
        for (int e = 0; e < 4; e++) {
            const int j = q * 4 + e;
            float h = ((const float*)&a)[e] + ((const float*)&b)[e] + __ldg(&b1[j]);
            h = fmaxf(h, 0.0f);
            o0 += h * __ldg(&W2[j * DOUT + 0]);
            o1 += h * __ldg(&W2[j * DOUT + 1]);
            o2 += h * __ldg(&W2[j * DOUT + 2]);
            o3 += h * __ldg(&W2[j * DOUT + 3]);
        }
    }
    ((float4*)HW2)[row] = make_float4(o0, o1, o2, o3);
}

// ---------------- Pass 2 (SIMT, memory-bound): logits = A @ HW2 + b2 ----------------
__global__ __launch_bounds__(256, 2)
void pass2_kernel(const float* __restrict__ A, const float* __restrict__ W,
                  const float* __restrict__ bias, float* __restrict__ out) {
    constexpr int NCOL = 4;
    constexpr int BM = 64, BK = 128;
    constexpr int STRIDE = 132;
    constexpr int NST = NROWS / BK;
    constexpr int ABUF = BM * STRIDE;
    constexpr int WBUF = BK * NCOL;

    extern __shared__ float fsm[];
    float* As[2] = { fsm, fsm + ABUF };
    float* Ws[2] = { fsm + 2 * ABUF, fsm + 2 * ABUF + WBUF };

    const int tid  = threadIdx.x;
    const int w    = tid >> 5;                // ksplit 0..7 (16 k's)
    const int lane = tid & 31;
    const int row0 = blockIdx.x * BM;

    auto load_stage = [&](int s) {
        const int buf = s & 1;
        const size_t kbase = (size_t)s * BK;
#pragma unroll
        for (int t = 0; t < 8; t++) {
            int idx = t * 256 + tid;
            int r = idx >> 5, c4 = idx & 31;
            cp_async16(As[buf] + r * STRIDE + c4 * 4,
                       A + (size_t)(row0 + r) * NROWS + kbase + c4 * 4);
        }
        if (tid < WBUF / 4)
            cp_async16(Ws[buf] + tid * 4, W + kbase * NCOL + tid * 4);
        cp_commit();
    };

    load_stage(0);
    load_stage(1);

    u64 acc[2][2] = {{0ull, 0ull}, {0ull, 0ull}};   // [rowhalf][colpair]

    for (int s = 0; s < NST; s++) {
        if (s + 1 < NST) cp_wait<1>(); else cp_wait<0>();
        __syncthreads();
        const int buf = s & 1;
        const float* ab = As[buf] + lane * STRIDE + w * 16;
        const float* wp = Ws[buf] + w * 16 * NCOL;
#pragma unroll
        for (int kh = 0; kh < 4; kh++) {
            float4 a0 = *(const float4*)(ab + kh * 4);
            float4 a1 = *(const float4*)(ab + 32 * STRIDE + kh * 4);
#pragma unroll
            for (int k2 = 0; k2 < 4; k2++) {
                const int k = kh * 4 + k2;
                ulonglong2 wv = *(const ulonglong2*)(wp + k * NCOL);  // warp-uniform
                u64 d0 = dup2(((const float*)&a0)[k2]);
                u64 d1 = dup2(((const float*)&a1)[k2]);
                fma2(acc[0][0], d0, wv.x);
                fma2(acc[0][1], d0, wv.y);
                fma2(acc[1][0], d1, wv.x);
                fma2(acc[1][1], d1, wv.y);
            }
        }
        __syncthreads();
        if (s + 2 < NST) load_stage(s + 2);
    }

    float* pbuf = fsm;                         // [8][64][4] = 8 KB
#pragma unroll
    for (int rh = 0; rh < 2; rh++)
        *(float4*)(pbuf + (size_t)(w * BM + lane + rh * 32) * NCOL) =
            make_float4(__uint_as_float((u32)acc[rh][0]),
                        __uint_as_float((u32)(acc[rh][0] >> 32)),
                        __uint_as_float((u32)acc[rh][1]),
                        __uint_as_float((u32)(acc[rh][1] >> 32)));
    __syncthreads();

    const int r = tid >> 2, c = tid & 3;
    float sum = 0.0f;
#pragma unroll
    for (int sp = 0; sp < 8; sp++) sum += pbuf[(size_t)(sp * BM + r) * NCOL + c];
    sum += __ldg(&bias[c]);
    out[(size_t)(row0 + r) * NCOL + c] = sum;
}

// ---------------- launch ----------------
extern "C" void kernel_launch(void* const* d_in, const int* in_sizes, int n_in,
                              void* d_out, int out_size) {
    const float* A  = (const float*)d_in[0];
    const float* X  = (const float*)d_in[1];
    const float* W1 = (const float*)d_in[2];
    const float* b1 = (const float*)d_in[3];
    const float* W2 = (const float*)d_in[4];
    const float* b2 = (const float*)d_in[5];
    float* out = (float*)d_out;

    float *wtp, *pp, *hw2p;
    cudaGetSymbolAddress((void**)&wtp, g_WT);
    cudaGetSymbolAddress((void**)&pp, g_P);
    cudaGetSymbolAddress((void**)&hw2p, g_HW2);

    // #0, #1: no-ops so ncu's captured launch (index 3) is pass1_mma
    dummy_a<<<1, 32>>>();
    dummy_b<<<1, 32>>>();

    // #2) WT = tf32-split (X @ W1)^T
    xw1t_kernel<<<NROWS / 32, 256>>>(X, W1, wtp);

    // #3) P = A @ XW1 partials   (mma.sync 3xTF32, 128 rowblocks x 2 k-halves)
    constexpr int SMEM_P1 = 2 * (128 * 68 + 32 * 68) * 4;    // 87040 B -> 2 CTAs/SM
    cudaFuncSetAttribute(pass1_mma, cudaFuncAttributeMaxDynamicSharedMemorySize, SMEM_P1);
    pass1_mma<<<256, 256, SMEM_P1>>>(A, wtp, pp);

    // #4) HW2 = relu(P0 + P1 + b1) @ W2
    combine_kernel<<<NROWS / 256, 256>>>(pp, b1, W2, hw2p);

    // #5) logits = A @ HW2 + b2           (SIMT, memory-bound)
    constexpr int SMEM_P2 = (2 * 64 * 132 + 2 * 128 * 4) * 4; // 71680 B
    cudaFuncSetAttribute(pass2_kernel, cudaFuncAttributeMaxDynamicSharedMemorySize, SMEM_P2);
    pass2_kernel<<<NROWS / 64, 256, SMEM_P2>>>(A, hw2p, b2, out);
}

// round 13
// speedup vs baseline: 1.0620x; 1.0010x over previous
#include <cuda_runtime.h>
#include <cstdint>
#include <cstddef>

#define NROWS 16384
#define DIN 128
#define DH 16
#define DOUT 4

typedef unsigned long long u64;
typedef unsigned int u32;

// Scratch (device globals: allocations are forbidden)
__device__ float g_WT[2 * DH * NROWS]; // rows 0-15: tf32_hi((X@W1)^T), rows 16-31: tf32_lo
__device__ float g_P[2 * NROWS * DH];  // pass1 partials: [khalf][row][16]
__device__ float g_HW2[NROWS * DOUT];  // relu(...) @ W2  [16384,4]

// ---------------- PTX helpers ----------------
__device__ __forceinline__ void cp_async16(void* smem_ptr, const void* gmem_ptr) {
    unsigned saddr = (unsigned)__cvta_generic_to_shared(smem_ptr);
    asm volatile("cp.async.cg.shared.global [%0], [%1], 16;\n" :: "r"(saddr), "l"(gmem_ptr));
}
__device__ __forceinline__ void cp_commit() { asm volatile("cp.async.commit_group;\n"); }
template <int N>
__device__ __forceinline__ void cp_wait() { asm volatile("cp.async.wait_group %0;\n" :: "n"(N)); }

__device__ __forceinline__ u64 dup2(float a) {
    u64 r; asm("mov.b64 %0, {%1, %1};" : "=l"(r) : "f"(a)); return r;
}
__device__ __forceinline__ void fma2(u64& acc, u64 a, u64 b) {
    asm("fma.rn.f32x2 %0, %1, %2, %0;" : "+l"(acc) : "l"(a), "l"(b));
}
__device__ __forceinline__ u32 cvt_tf32(float x) {
    u32 r; asm("cvt.rna.tf32.f32 %0, %1;" : "=r"(r) : "f"(x)); return r;
}
// m16n8k8 tf32 HMMA (base sm_80+ ISA, valid on non-'a' sm_103 target)
__device__ __forceinline__ void mma_tf32(float4& d, u32 a0, u32 a1, u32 a2, u32 a3,
                                         u32 b0, u32 b1) {
    asm volatile("mma.sync.aligned.m16n8k8.row.col.f32.tf32.tf32.f32 "
                 "{%0,%1,%2,%3}, {%4,%5,%6,%7}, {%8,%9}, {%0,%1,%2,%3};"
                 : "+f"(d.x), "+f"(d.y), "+f"(d.z), "+f"(d.w)
                 : "r"(a0), "r"(a1), "r"(a2), "r"(a3), "r"(b0), "r"(b1));
}

// Diagnostic no-ops: ncu profiles launch index 3 -> land it on pass1_mma.
__global__ void dummy_a() {}
__global__ void dummy_b() {}

// ---------------- Kernel 0: WT_hi/lo = tf32-split of (X @ W1)^T ----------------
__global__ __launch_bounds__(256)
void xw1t_kernel(const float* __restrict__ X, const float* __restrict__ W1,
                 float* __restrict__ WT) {
    __shared__ float xs[32 * DIN];
    __shared__ float w1s[DIN * DH];
    const int tid = threadIdx.x;
    for (int i = tid; i < DIN * DH / 2; i += 256)
        ((float2*)w1s)[i] = ((const float2*)W1)[i];
    const float4* xg = (const float4*)(X + (size_t)blockIdx.x * 32 * DIN);
#pragma unroll
    for (int t = 0; t < 4; t++)
        ((float4*)xs)[t * 256 + tid] = xg[t * 256 + tid];
    __syncthreads();
#pragma unroll
    for (int t = 0; t < 2; t++) {
        int i = t * 256 + tid;
        int r = i >> 4, c = i & 15;
        float acc = 0.0f;
#pragma unroll
        for (int k = 0; k < DIN; k++) acc += xs[r * DIN + k] * w1s[k * DH + c];
        u32 hi = cvt_tf32(acc);
        float lo = acc - __uint_as_float(hi);
        size_t col = (size_t)blockIdx.x * 32 + r;
        WT[(size_t)c * NROWS + col]        = __uint_as_float(hi);
        WT[(size_t)(DH + c) * NROWS + col] = __uint_as_float(cvt_tf32(lo));
    }
}

// ---------------- Pass 1 (HMMA 3xTF32, CTA K-split): P = A @ XW1 partials ----------------
// grid 256 = (row-block 0..127) x (k-half 0..1); 2 CTAs co-resident per SM.
// BM=128, BK=64, double-buffer; 8 warps = (ksplit 0..3) x (m-half 0..1).
__global__ __launch_bounds__(256, 2)
void pass1_mma(const float* __restrict__ A, const float* __restrict__ WT,
               float* __restrict__ P) {
    constexpr int BM = 128, BK = 64;
    constexpr int STRIDE = 68;                // 64 + 4 pad: conflict-free
    constexpr int KSPAN = NROWS / 2;          // 8192 per CTA
    constexpr int NST = KSPAN / BK;           // 128
    constexpr int ABUF = BM * STRIDE;         // 8704 floats
    constexpr int WBUF = 2 * DH * STRIDE;     // 2176 floats (hi+lo)
    constexpr int SB = ABUF + WBUF;           // 10880 floats/stage -> 87 KB total

    extern __shared__ float fsm[];
    const int tid  = threadIdx.x;
    const int w    = tid >> 5;
    const int lane = tid & 31;
    const int gid  = lane >> 2;               // 0..7
    const int tig  = lane & 3;                // 0..3
    const int ks   = w & 3;                   // k offset = ks*16 within BK=64
    const int mh   = w >> 2;                  // m-half: tiles mh*4 .. mh*4+3
    const int rb   = blockIdx.x >> 1;         // row block
    const int kc   = blockIdx.x & 1;          // k half
    const int row0 = rb * BM;
    const size_t kbase0 = (size_t)kc * KSPAN;

    auto load_stage = [&](int s) {
        float* base = fsm + (s & 1) * SB;
        const size_t kb = kbase0 + (size_t)s * BK;
        // A: 128 rows x 16 chunks(16B) = 2048 float4, 8 per thread
#pragma unroll
        for (int t = 0; t < 8; t++) {
            int idx = t * 256 + tid;
            int r = idx >> 4, c4 = idx & 15;
            cp_async16(base + r * STRIDE + c4 * 4,
                       A + (size_t)(row0 + r) * NROWS + kb + c4 * 4);
        }
        // WT hi+lo: 32 rows x 16 chunks = 512 float4, 2 per thread
#pragma unroll
        for (int t = 0; t < 2; t++) {
            int idx = t * 256 + tid;
            int r = idx >> 4, c4 = idx & 15;
            cp_async16(base + ABUF + r * STRIDE + c4 * 4,
                       WT + (size_t)r * NROWS + kb + c4 * 4);
        }
        cp_commit();
    };

    load_stage(0);
    load_stage(1);

    float4 C[4][2];                            // [mtile within half][ntile]
#pragma unroll
    for (int m = 0; m < 4; m++)
#pragma unroll
        for (int n = 0; n < 2; n++) C[m][n] = make_float4(0.f, 0.f, 0.f, 0.f);

    for (int s = 0; s < NST; s++) {
        if (s + 1 < NST) cp_wait<1>(); else cp_wait<0>();
        __syncthreads();
        const float* base = fsm + (s & 1) * SB;
#pragma unroll
        for (int k8 = 0; k8 < 2; k8++) {       // warp covers 16 k's = 2 k8 steps
            const int k0 = ks * 16 + k8 * 8;
            const float* bh = base + ABUF + gid * STRIDE + k0 + tig;
            const float* bl = bh + DH * STRIDE;
            u32 bh00 = __float_as_uint(bh[0]);
            u32 bh01 = __float_as_uint(bh[4]);
            u32 bh10 = __float_as_uint(bh[8 * STRIDE]);
            u32 bh11 = __float_as_uint(bh[8 * STRIDE + 4]);
            u32 bl00 = __float_as_uint(bl[0]);
            u32 bl01 = __float_as_uint(bl[4]);
            u32 bl10 = __float_as_uint(bl[8 * STRIDE]);
            u32 bl11 = __float_as_uint(bl[8 * STRIDE + 4]);
#pragma unroll
            for (int mt = 0; mt < 4; mt++) {
                const float* ap = base + (mh * 64 + mt * 16 + gid) * STRIDE + k0 + tig;
                float av0 = ap[0], av1 = ap[8 * STRIDE], av2 = ap[4], av3 = ap[8 * STRIDE + 4];
                u32 ah0 = cvt_tf32(av0), ah1 = cvt_tf32(av1);
                u32 ah2 = cvt_tf32(av2), ah3 = cvt_tf32(av3);
                u32 al0 = cvt_tf32(av0 - __uint_as_float(ah0));
                u32 al1 = cvt_tf32(av1 - __uint_as_float(ah1));
                u32 al2 = cvt_tf32(av2 - __uint_as_float(ah2));
                u32 al3 = cvt_tf32(av3 - __uint_as_float(ah3));
                mma_tf32(C[mt][0], ah0, ah1, ah2, ah3, bh00, bh01);
                mma_tf32(C[mt][0], al0, al1, al2, al3, bh00, bh01);
                mma_tf32(C[mt][0], ah0, ah1, ah2, ah3, bl00, bl01);
                mma_tf32(C[mt][1], ah0, ah1, ah2, ah3, bh10, bh11);
                mma_tf32(C[mt][1], al0, al1, al2, al3, bh10, bh11);
                mma_tf32(C[mt][1], ah0, ah1, ah2, ah3, bl10, bl11);
            }
        }
        __syncthreads();
        if (s + 2 < NST) load_stage(s + 2); else cp_commit();
    }

    // ---- epilogue: reduce 4 ksplit partials, write raw partial sums ----
    float* psum = fsm;                         // [4][128][16] = 32 KB
    {
        float* p = psum + ks * (BM * DH);
#pragma unroll
        for (int mt = 0; mt < 4; mt++) {
            const int rbm = mh * 64 + mt * 16 + gid;
            *(float2*)(p + rbm * DH + 2 * tig)           = make_float2(C[mt][0].x, C[mt][0].y);
            *(float2*)(p + (rbm + 8) * DH + 2 * tig)     = make_float2(C[mt][0].z, C[mt][0].w);
            *(float2*)(p + rbm * DH + 8 + 2 * tig)       = make_float2(C[mt][1].x, C[mt][1].y);
            *(float2*)(p + (rbm + 8) * DH + 8 + 2 * tig) = make_float2(C[mt][1].z, C[mt][1].w);
        }
    }
    __syncthreads();
    float* Pout = P + ((size_t)kc * NROWS + row0) * DH;
#pragma unroll
    for (int t = 0; t < 8; t++) {
        int i = t * 256 + tid;                 // 2048 values, coalesced
        float sum = 0.0f;
#pragma unroll
        for (int sp = 0; sp < 4; sp++) sum += psum[sp * (BM * DH) + i];
        Pout[i] = sum;
    }
}

// ---------------- Combine: HW2 = relu(P0 + P1 + b1) @ W2 ----------------
__global__ __launch_bounds__(256)
void combine_kernel(const float* __restrict__ P, const float* __restrict__ b1,
                    const float* __restrict__ W2, float* __restrict__ HW2) {
    const int row = blockIdx.x * 256 + threadIdx.x;
    const float4* p0 = (const float4*)(P + (size_t)row * DH);
    const float4* p1 = (const float4*)(P + (size_t)(NROWS + row) * DH);
    float o0 = 0.f, o1 = 0.f, o2 = 0.f, o3 = 0.f;
#pragma unroll
    for (int q = 0; q < 4; q++) {
        float4 a = p0[q], b = p1[q];
#pragma unroll
        for (int e = 0; e < 4; e++) {
            const int j = q * 4 + e;
            float h = ((const float*)&a)[e] + ((const float*)&b)[e] + __ldg(&b1[j]);
            h = fmaxf(h, 0.0f);
            o0 += h * __ldg(&W2[j * DOUT + 0]);
            o1 += h * __ldg(&W2[j * DOUT + 1]);
            o2 += h * __ldg(&W2[j * DOUT + 2]);
            o3 += h * __ldg(&W2[j * DOUT + 3]);
        }
    }
    ((float4*)HW2)[row] = make_float4(o0, o1, o2, o3);
}

// ---------------- Pass 2 (SIMT, memory-bound): logits = A @ HW2 + b2 ----------------
__global__ __launch_bounds__(256, 2)
void pass2_kernel(const float* __restrict__ A, const float* __restrict__ W,
                  const float* __restrict__ bias, float* __restrict__ out) {
    constexpr int NCOL = 4;
    constexpr int BM = 64, BK = 128;
    constexpr int STRIDE = 132;
    constexpr int NST = NROWS / BK;
    constexpr int ABUF = BM * STRIDE;
    constexpr int WBUF = BK * NCOL;

    extern __shared__ float fsm[];
    float* As[2] = { fsm, fsm + ABUF };
    float* Ws[2] = { fsm + 2 * ABUF, fsm + 2 * ABUF + WBUF };

    const int tid  = threadIdx.x;
    const int w    = tid >> 5;                // ksplit 0..7 (16 k's)
    const int lane = tid & 31;
    const int row0 = blockIdx.x * BM;

    auto load_stage = [&](int s) {
        const int buf = s & 1;
        const size_t kbase = (size_t)s * BK;
#pragma unroll
        for (int t = 0; t < 8; t++) {
            int idx = t * 256 + tid;
            int r = idx >> 5, c4 = idx & 31;
            cp_async16(As[buf] + r * STRIDE + c4 * 4,
                       A + (size_t)(row0 + r) * NROWS + kbase + c4 * 4);
        }
        if (tid < WBUF / 4)
            cp_async16(Ws[buf] + tid * 4, W + kbase * NCOL + tid * 4);
        cp_commit();
    };

    load_stage(0);
    load_stage(1);

    u64 acc[2][2] = {{0ull, 0ull}, {0ull, 0ull}};   // [rowhalf][colpair]

    for (int s = 0; s < NST; s++) {
        if (s + 1 < NST) cp_wait<1>(); else cp_wait<0>();
        __syncthreads();
        const int buf = s & 1;
        const float* ab = As[buf] + lane * STRIDE + w * 16;
        const float* wp = Ws[buf] + w * 16 * NCOL;
#pragma unroll
        for (int kh = 0; kh < 4; kh++) {
            float4 a0 = *(const float4*)(ab + kh * 4);
            float4 a1 = *(const float4*)(ab + 32 * STRIDE + kh * 4);
#pragma unroll
            for (int k2 = 0; k2 < 4; k2++) {
                const int k = kh * 4 + k2;
                ulonglong2 wv = *(const ulonglong2*)(wp + k * NCOL);  // warp-uniform
                u64 d0 = dup2(((const float*)&a0)[k2]);
                u64 d1 = dup2(((const float*)&a1)[k2]);
                fma2(acc[0][0], d0, wv.x);
                fma2(acc[0][1], d0, wv.y);
                fma2(acc[1][0], d1, wv.x);
                fma2(acc[1][1], d1, wv.y);
            }
        }
        __syncthreads();
        if (s + 2 < NST) load_stage(s + 2);
    }

    float* pbuf = fsm;                         // [8][64][4] = 8 KB
#pragma unroll
    for (int rh = 0; rh < 2; rh++)
        *(float4*)(pbuf + (size_t)(w * BM + lane + rh * 32) * NCOL) =
            make_float4(__uint_as_float((u32)acc[rh][0]),
                        __uint_as_float((u32)(acc[rh][0] >> 32)),
                        __uint_as_float((u32)acc[rh][1]),
                        __uint_as_float((u32)(acc[rh][1] >> 32)));
    __syncthreads();

    const int r = tid >> 2, c = tid & 3;
    float sum = 0.0f;
#pragma unroll
    for (int sp = 0; sp < 8; sp++) sum += pbuf[(size_t)(sp * BM + r) * NCOL + c];
    sum += __ldg(&bias[c]);
    out[(size_t)(row0 + r) * NCOL + c] = sum;
}

// ---------------- launch ----------------
extern "C" void kernel_launch(void* const* d_in, const int* in_sizes, int n_in,
                              void* d_out, int out_size) {
    const float* A  = (const float*)d_in[0];
    const float* X  = (const float*)d_in[1];
    const float* W1 = (const float*)d_in[2];
    const float* b1 = (const float*)d_in[3];
    const float* W2 = (const float*)d_in[4];
    const float* b2 = (const float*)d_in[5];
    float* out = (float*)d_out;

    float *wtp, *pp, *hw2p;
    cudaGetSymbolAddress((void**)&wtp, g_WT);
    cudaGetSymbolAddress((void**)&pp, g_P);
    cudaGetSymbolAddress((void**)&hw2p, g_HW2);

    // #0, #1: no-ops so ncu's captured launch (index 3) is pass1_mma
    dummy_a<<<1, 32>>>();
    dummy_b<<<1, 32>>>();

    // #2) WT = tf32-split (X @ W1)^T
    xw1t_kernel<<<NROWS / 32, 256>>>(X, W1, wtp);

    // #3) P = A @ XW1 partials   (mma.sync 3xTF32, 128 rowblocks x 2 k-halves)
    constexpr int SMEM_P1 = 2 * (128 * 68 + 32 * 68) * 4;    // 87040 B -> 2 CTAs/SM
    cudaFuncSetAttribute(pass1_mma, cudaFuncAttributeMaxDynamicSharedMemorySize, SMEM_P1);
    pass1_mma<<<256, 256, SMEM_P1>>>(A, wtp, pp);

    // #4) HW2 = relu(P0 + P1 + b1) @ W2
    combine_kernel<<<NROWS / 256, 256>>>(pp, b1, W2, hw2p);

    // #5) logits = A @ HW2 + b2           (SIMT, memory-bound)
    constexpr int SMEM_P2 = (2 * 64 * 132 + 2 * 128 * 4) * 4; // 71680 B
    cudaFuncSetAttribute(pass2_kernel, cudaFuncAttributeMaxDynamicSharedMemorySize, SMEM_P2);
    pass2_kernel<<<NROWS / 64, 256, SMEM_P2>>>(A, hw2p, b2, out);
}

// round 14
// speedup vs baseline: 1.1053x; 1.0408x over previous
#include <cuda_runtime.h>
#include <cstdint>
#include <cstddef>

#define NROWS 16384
#define DIN 128
#define DH 16
#define DOUT 4

typedef unsigned long long u64;
typedef unsigned int u32;

// Scratch (device globals: allocations are forbidden)
__device__ float g_WT[2 * DH * NROWS]; // rows 0-15: tf32_hi((X@W1)^T), rows 16-31: tf32_lo
__device__ float g_P[2 * NROWS * DH];  // pass1 partials: [khalf][row][16]
__device__ float g_HW2[NROWS * DOUT];  // relu(...) @ W2  [16384,4]

// ---------------- PTX helpers ----------------
__device__ __forceinline__ void cp_async16(void* smem_ptr, const void* gmem_ptr) {
    unsigned saddr = (unsigned)__cvta_generic_to_shared(smem_ptr);
    asm volatile("cp.async.cg.shared.global [%0], [%1], 16;\n" :: "r"(saddr), "l"(gmem_ptr));
}
__device__ __forceinline__ void cp_commit() { asm volatile("cp.async.commit_group;\n"); }
template <int N>
__device__ __forceinline__ void cp_wait() { asm volatile("cp.async.wait_group %0;\n" :: "n"(N)); }

__device__ __forceinline__ u64 dup2(float a) {
    u64 r; asm("mov.b64 %0, {%1, %1};" : "=l"(r) : "f"(a)); return r;
}
__device__ __forceinline__ void fma2(u64& acc, u64 a, u64 b) {
    asm("fma.rn.f32x2 %0, %1, %2, %0;" : "+l"(acc) : "l"(a), "l"(b));
}
__device__ __forceinline__ u32 cvt_tf32(float x) {
    u32 r; asm("cvt.rna.tf32.f32 %0, %1;" : "=r"(r) : "f"(x)); return r;
}
// m16n8k8 tf32 HMMA (base sm_80+ ISA, valid on non-'a' sm_103 target)
__device__ __forceinline__ void mma_tf32(float4& d, u32 a0, u32 a1, u32 a2, u32 a3,
                                         u32 b0, u32 b1) {
    asm volatile("mma.sync.aligned.m16n8k8.row.col.f32.tf32.tf32.f32 "
                 "{%0,%1,%2,%3}, {%4,%5,%6,%7}, {%8,%9}, {%0,%1,%2,%3};"
                 : "+f"(d.x), "+f"(d.y), "+f"(d.z), "+f"(d.w)
                 : "r"(a0), "r"(a1), "r"(a2), "r"(a3), "r"(b0), "r"(b1));
}

// Diagnostic no-ops: ncu profiles launch index 3 -> land it on pass1_mma.
__global__ void dummy_a() {}
__global__ void dummy_b() {}

// ---------------- Kernel 0: WT_hi/lo = tf32-split of (X @ W1)^T ----------------
__global__ __launch_bounds__(256)
void xw1t_kernel(const float* __restrict__ X, const float* __restrict__ W1,
                 float* __restrict__ WT) {
    __shared__ float xs[32 * DIN];
    __shared__ float w1s[DIN * DH];
    const int tid = threadIdx.x;
    for (int i = tid; i < DIN * DH / 2; i += 256)
        ((float2*)w1s)[i] = ((const float2*)W1)[i];
    const float4* xg = (const float4*)(X + (size_t)blockIdx.x * 32 * DIN);
#pragma unroll
    for (int t = 0; t < 4; t++)
        ((float4*)xs)[t * 256 + tid] = xg[t * 256 + tid];
    __syncthreads();
#pragma unroll
    for (int t = 0; t < 2; t++) {
        int i = t * 256 + tid;
        int r = i >> 4, c = i & 15;
        float acc = 0.0f;
#pragma unroll
        for (int k = 0; k < DIN; k++) acc += xs[r * DIN + k] * w1s[k * DH + c];
        u32 hi = cvt_tf32(acc);
        float lo = acc - __uint_as_float(hi);
        size_t col = (size_t)blockIdx.x * 32 + r;
        WT[(size_t)c * NROWS + col]        = __uint_as_float(hi);
        WT[(size_t)(DH + c) * NROWS + col] = __uint_as_float(cvt_tf32(lo));
    }
}

// ---------------- Pass 1 (HMMA 3xTF32, CTA K-split): P = A @ XW1 partials ----------------
// grid 256 = (row-block 0..127) x (k-half 0..1); 2 CTAs co-resident per SM.
// BM=128, BK=32, NBUF=4, loads issued BEFORE compute each iter (latency hiding).
__global__ __launch_bounds__(256, 2)
void pass1_mma(const float* __restrict__ A, const float* __restrict__ WT,
               float* __restrict__ P) {
    constexpr int BM = 128, BK = 32;
    constexpr int STRIDE = 36;                // 32 + 4 pad: conflict-free scalar LDS
    constexpr int KSPAN = NROWS / 2;          // 8192 per CTA
    constexpr int NST = KSPAN / BK;           // 256
    constexpr int ABUF = BM * STRIDE;         // 4608 floats
    constexpr int WBUF = 2 * DH * STRIDE;     // 1152 floats (hi+lo)
    constexpr int SB = ABUF + WBUF;           // 5760 floats/stage
    constexpr int NBUF = 4;                   // 92160 B total -> 2 CTAs/SM

    extern __shared__ float fsm[];
    const int tid  = threadIdx.x;
    const int w    = tid >> 5;
    const int lane = tid & 31;
    const int gid  = lane >> 2;               // 0..7
    const int tig  = lane & 3;                // 0..3
    const int ks   = w & 3;                   // k offset = ks*8 within BK=32
    const int mh   = w >> 2;                  // m-half: tiles mh*4 .. mh*4+3
    const int rb   = blockIdx.x >> 1;         // row block
    const int kc   = blockIdx.x & 1;          // k half
    const int row0 = rb * BM;
    const size_t kbase0 = (size_t)kc * KSPAN;

    auto load_stage = [&](int s) {
        float* base = fsm + (s & (NBUF - 1)) * SB;
        const size_t kb = kbase0 + (size_t)s * BK;
        // A: 128 rows x 8 chunks(16B) = 1024 float4, 4 per thread
#pragma unroll
        for (int t = 0; t < 4; t++) {
            int idx = t * 256 + tid;
            int r = idx >> 3, c4 = idx & 7;
            cp_async16(base + r * STRIDE + c4 * 4,
                       A + (size_t)(row0 + r) * NROWS + kb + c4 * 4);
        }
        // WT hi+lo: 32 rows x 8 chunks = 256 float4, 1 per thread
        {
            int r = tid >> 3, c4 = tid & 7;
            cp_async16(base + ABUF + r * STRIDE + c4 * 4,
                       WT + (size_t)r * NROWS + kb + c4 * 4);
        }
        cp_commit();
    };

    load_stage(0);
    load_stage(1);
    load_stage(2);

    float4 C[4][2];                            // [mtile within half][ntile]
#pragma unroll
    for (int m = 0; m < 4; m++)
#pragma unroll
        for (int n = 0; n < 2; n++) C[m][n] = make_float4(0.f, 0.f, 0.f, 0.f);

    for (int s = 0; s < NST; s++) {
        cp_wait<2>();                          // group s complete (3 prologue + 1/iter)
        __syncthreads();
        // issue loads FIRST: buffer (s+3)%4 is free (compute(s-1) done at last sync)
        if (s + 3 < NST) load_stage(s + 3); else cp_commit();

        const float* base = fsm + (s & (NBUF - 1)) * SB;
        const int k0 = ks * 8;
        const float* bh = base + ABUF + gid * STRIDE + k0 + tig;
        const float* bl = bh + DH * STRIDE;
        u32 bh00 = __float_as_uint(bh[0]);
        u32 bh01 = __float_as_uint(bh[4]);
        u32 bh10 = __float_as_uint(bh[8 * STRIDE]);
        u32 bh11 = __float_as_uint(bh[8 * STRIDE + 4]);
        u32 bl00 = __float_as_uint(bl[0]);
        u32 bl01 = __float_as_uint(bl[4]);
        u32 bl10 = __float_as_uint(bl[8 * STRIDE]);
        u32 bl11 = __float_as_uint(bl[8 * STRIDE + 4]);
#pragma unroll
        for (int mt = 0; mt < 4; mt++) {
            const float* ap = base + (mh * 64 + mt * 16 + gid) * STRIDE + k0 + tig;
            float av0 = ap[0], av1 = ap[8 * STRIDE], av2 = ap[4], av3 = ap[8 * STRIDE + 4];
            u32 ah0 = cvt_tf32(av0), ah1 = cvt_tf32(av1);
            u32 ah2 = cvt_tf32(av2), ah3 = cvt_tf32(av3);
            u32 al0 = cvt_tf32(av0 - __uint_as_float(ah0));
            u32 al1 = cvt_tf32(av1 - __uint_as_float(ah1));
            u32 al2 = cvt_tf32(av2 - __uint_as_float(ah2));
            u32 al3 = cvt_tf32(av3 - __uint_as_float(ah3));
            mma_tf32(C[mt][0], ah0, ah1, ah2, ah3, bh00, bh01);
            mma_tf32(C[mt][0], al0, al1, al2, al3, bh00, bh01);
            mma_tf32(C[mt][0], ah0, ah1, ah2, ah3, bl00, bl01);
            mma_tf32(C[mt][1], ah0, ah1, ah2, ah3, bh10, bh11);
            mma_tf32(C[mt][1], al0, al1, al2, al3, bh10, bh11);
            mma_tf32(C[mt][1], ah0, ah1, ah2, ah3, bl10, bl11);
        }
        __syncthreads();
    }

    // ---- epilogue: reduce 4 ksplit partials, write raw partial sums ----
    float* psum = fsm;                         // [4][128][16] = 32 KB
    {
        float* p = psum + ks * (BM * DH);
#pragma unroll
        for (int mt = 0; mt < 4; mt++) {
            const int rbm = mh * 64 + mt * 16 + gid;
            *(float2*)(p + rbm * DH + 2 * tig)           = make_float2(C[mt][0].x, C[mt][0].y);
            *(float2*)(p + (rbm + 8) * DH + 2 * tig)     = make_float2(C[mt][0].z, C[mt][0].w);
            *(float2*)(p + rbm * DH + 8 + 2 * tig)       = make_float2(C[mt][1].x, C[mt][1].y);
            *(float2*)(p + (rbm + 8) * DH + 8 + 2 * tig) = make_float2(C[mt][1].z, C[mt][1].w);
        }
    }
    __syncthreads();
    float* Pout = P + ((size_t)kc * NROWS + row0) * DH;
#pragma unroll
    for (int t = 0; t < 8; t++) {
        int i = t * 256 + tid;                 // 2048 values, coalesced
        float sum = 0.0f;
#pragma unroll
        for (int sp = 0; sp < 4; sp++) sum += psum[sp * (BM * DH) + i];
        Pout[i] = sum;
    }
}

// ---------------- Combine: HW2 = relu(P0 + P1 + b1) @ W2 ----------------
__global__ __launch_bounds__(256)
void combine_kernel(const float* __restrict__ P, const float* __restrict__ b1,
                    const float* __restrict__ W2, float* __restrict__ HW2) {
    const int row = blockIdx.x * 256 + threadIdx.x;
    const float4* p0 = (const float4*)(P + (size_t)row * DH);
    const float4* p1 = (const float4*)(P + (size_t)(NROWS + row) * DH);
    float o0 = 0.f, o1 = 0.f, o2 = 0.f, o3 = 0.f;
#pragma unroll
    for (int q = 0; q < 4; q++) {
        float4 a = p0[q], b = p1[q];
#pragma unroll
        for (int e = 0; e < 4; e++) {
            const int j = q * 4 + e;
            float h = ((const float*)&a)[e] + ((const float*)&b)[e] + __ldg(&b1[j]);
            h = fmaxf(h, 0.0f);
            o0 += h * __ldg(&W2[j * DOUT + 0]);
            o1 += h * __ldg(&W2[j * DOUT + 1]);
            o2 += h * __ldg(&W2[j * DOUT + 2]);
            o3 += h * __ldg(&W2[j * DOUT + 3]);
        }
    }
    ((float4*)HW2)[row] = make_float4(o0, o1, o2, o3);
}

// ---------------- Pass 2 (SIMT, memory-bound): logits = A @ HW2 + b2 ----------------
// NBUF=3 with loads issued before compute (same latency-hiding schedule).
__global__ __launch_bounds__(256, 2)
void pass2_kernel(const float* __restrict__ A, const float* __restrict__ W,
                  const float* __restrict__ bias, float* __restrict__ out) {
    constexpr int NCOL = 4;
    constexpr int BM = 64, BK = 128;
    constexpr int STRIDE = 132;
    constexpr int NST = NROWS / BK;
    constexpr int ABUF = BM * STRIDE;         // 8448 floats
    constexpr int WBUF = BK * NCOL;           // 512 floats
    constexpr int SB = ABUF + WBUF;           // 8960 floats/stage
    constexpr int NBUF = 3;                   // 107520 B total -> 2 CTAs/SM

    extern __shared__ float fsm[];
    const int tid  = threadIdx.x;
    const int w    = tid >> 5;                // ksplit 0..7 (16 k's)
    const int lane = tid & 31;
    const int row0 = blockIdx.x * BM;

    auto load_stage = [&](int s) {
        float* base = fsm + (s % NBUF) * SB;
        const size_t kbase = (size_t)s * BK;
#pragma unroll
        for (int t = 0; t < 8; t++) {
            int idx = t * 256 + tid;
            int r = idx >> 5, c4 = idx & 31;
            cp_async16(base + r * STRIDE + c4 * 4,
                       A + (size_t)(row0 + r) * NROWS + kbase + c4 * 4);
        }
        if (tid < WBUF / 4)
            cp_async16(base + ABUF + tid * 4, W + kbase * NCOL + tid * 4);
        cp_commit();
    };

    load_stage(0);
    load_stage(1);

    u64 acc[2][2] = {{0ull, 0ull}, {0ull, 0ull}};   // [rowhalf][colpair]

    for (int s = 0; s < NST; s++) {
        cp_wait<1>();                          // group s complete (2 prologue + 1/iter)
        __syncthreads();
        if (s + 2 < NST) load_stage(s + 2); else cp_commit();

        const float* base = fsm + (s % NBUF) * SB;
        const float* ab = base + lane * STRIDE + w * 16;
        const float* wp = base + ABUF + w * 16 * NCOL;
#pragma unroll
        for (int kh = 0; kh < 4; kh++) {
            float4 a0 = *(const float4*)(ab + kh * 4);
            float4 a1 = *(const float4*)(ab + 32 * STRIDE + kh * 4);
#pragma unroll
            for (int k2 = 0; k2 < 4; k2++) {
                const int k = kh * 4 + k2;
                ulonglong2 wv = *(const ulonglong2*)(wp + k * NCOL);  // warp-uniform
                u64 d0 = dup2(((const float*)&a0)[k2]);
                u64 d1 = dup2(((const float*)&a1)[k2]);
                fma2(acc[0][0], d0, wv.x);
                fma2(acc[0][1], d0, wv.y);
                fma2(acc[1][0], d1, wv.x);
                fma2(acc[1][1], d1, wv.y);
            }
        }
        __syncthreads();
    }

    float* pbuf = fsm;                         // [8][64][4] = 8 KB
#pragma unroll
    for (int rh = 0; rh < 2; rh++)
        *(float4*)(pbuf + (size_t)(w * BM + lane + rh * 32) * NCOL) =
            make_float4(__uint_as_float((u32)acc[rh][0]),
                        __uint_as_float((u32)(acc[rh][0] >> 32)),
                        __uint_as_float((u32)acc[rh][1]),
                        __uint_as_float((u32)(acc[rh][1] >> 32)));
    __syncthreads();

    const int r = tid >> 2, c = tid & 3;
    float sum = 0.0f;
#pragma unroll
    for (int sp = 0; sp < 8; sp++) sum += pbuf[(size_t)(sp * BM + r) * NCOL + c];
    sum += __ldg(&bias[c]);
    out[(size_t)(row0 + r) * NCOL + c] = sum;
}

// ---------------- launch ----------------
extern "C" void kernel_launch(void* const* d_in, const int* in_sizes, int n_in,
                              void* d_out, int out_size) {
    const float* A  = (const float*)d_in[0];
    const float* X  = (const float*)d_in[1];
    const float* W1 = (const float*)d_in[2];
    const float* b1 = (const float*)d_in[3];
    const float* W2 = (const float*)d_in[4];
    const float* b2 = (const float*)d_in[5];
    float* out = (float*)d_out;

    float *wtp, *pp, *hw2p;
    cudaGetSymbolAddress((void**)&wtp, g_WT);
    cudaGetSymbolAddress((void**)&pp, g_P);
    cudaGetSymbolAddress((void**)&hw2p, g_HW2);

    // #0, #1: no-ops so ncu's captured launch (index 3) is pass1_mma
    dummy_a<<<1, 32>>>();
    dummy_b<<<1, 32>>>();

    // #2) WT = tf32-split (X @ W1)^T
    xw1t_kernel<<<NROWS / 32, 256>>>(X, W1, wtp);

    // #3) P = A @ XW1 partials   (mma.sync 3xTF32, 128 rowblocks x 2 k-halves)
    constexpr int SMEM_P1 = 4 * (128 * 36 + 32 * 36) * 4;    // 92160 B -> 2 CTAs/SM
    cudaFuncSetAttribute(pass1_mma, cudaFuncAttributeMaxDynamicSharedMemorySize, SMEM_P1);
    pass1_mma<<<256, 256, SMEM_P1>>>(A, wtp, pp);

    // #4) HW2 = relu(P0 + P1 + b1) @ W2
    combine_kernel<<<NROWS / 256, 256>>>(pp, b1, W2, hw2p);

    // #5) logits = A @ HW2 + b2           (SIMT, memory-bound)
    constexpr int SMEM_P2 = 3 * (64 * 132 + 128 * 4) * 4;    // 107520 B -> 2 CTAs/SM
    cudaFuncSetAttribute(pass2_kernel, cudaFuncAttributeMaxDynamicSharedMemorySize, SMEM_P2);
    pass2_kernel<<<NROWS / 64, 256, SMEM_P2>>>(A, hw2p, b2, out);
}